// round 1
// baseline (speedup 1.0000x reference)
#include <cuda_runtime.h>
#include <stdint.h>
#include <math.h>

#define BATCH 8
#define NANCH 100000
#define NGT   64
#define NTOK  256
#define TOPK  27
#define NEG_INF -100000000.0f

// ---------------- device scratch (no allocations allowed) ----------------
__device__ float2             g_centers[BATCH * NANCH];      // anchor centers
__device__ unsigned long long g_match[BATCH * NANCH];        // packed (iou_bits<<32 | 63-g), 0 = unmatched
__device__ int                g_cand_idx[BATCH * NGT * TOPK];
__device__ float              g_cand_iou[BATCH * NGT * TOPK]; // -1 if not positive

// ---------------- kernel 0: anchor centers ----------------
__global__ void centers_kernel(const float* __restrict__ anchors) {
    int i = blockIdx.x * blockDim.x + threadIdx.x;
    if (i < BATCH * NANCH) {
        float4 a = ((const float4*)anchors)[i];
        g_centers[i] = make_float2((a.x + a.z) * 0.5f, (a.y + a.w) * 0.5f);
    }
}

// ---------------- kernel 1: per-(b,g) top-27 nearest anchors + IoU stats ----------------
__global__ __launch_bounds__(128) void topk_kernel(const float* __restrict__ anchors,
                                                   const float* __restrict__ gts) {
    const int bg = blockIdx.x;
    const int b  = bg / NGT;
    const int t  = threadIdx.x;

    const float4 gt = ((const float4*)gts)[bg];
    const float gcx = (gt.x + gt.z) * 0.5f;
    const float gcy = (gt.y + gt.w) * 0.5f;

    // per-thread sorted top-27 of packed (dist2_bits << 32 | anchor_idx)
    unsigned long long best[TOPK];
#pragma unroll
    for (int k = 0; k < TOPK; k++) best[k] = 0xFFFFFFFFFFFFFFFFULL;

    const float2* __restrict__ cen = g_centers + b * NANCH;
    for (int n = t; n < NANCH; n += 128) {
        float2 c = cen[n];
        float dx = c.x - gcx, dy = c.y - gcy;
        float d2 = dx * dx + dy * dy;                     // positive -> bit pattern is order-preserving
        unsigned long long p =
            (((unsigned long long)__float_as_uint(d2)) << 32) | (unsigned)n;
        if (p < best[TOPK - 1]) {
#pragma unroll
            for (int k = TOPK - 1; k >= 0; --k) {
                if (k == 0 || p >= best[k - 1]) { best[k] = p; break; }
                best[k] = best[k - 1];
            }
        }
    }

    // merge 128 sorted lists: 27 rounds of head-min reduction
    __shared__ unsigned long long cand[128 * TOPK];
    __shared__ unsigned long long red[128];
    __shared__ int   res[TOPK];
    __shared__ float siou[TOPK];
    __shared__ int   sing[TOPK];
    __shared__ float sthr;

#pragma unroll
    for (int k = 0; k < TOPK; k++) cand[t * TOPK + k] = best[k];
    __syncthreads();

    int head = 0;
    for (int r = 0; r < TOPK; r++) {
        unsigned long long c = (head < TOPK) ? cand[t * TOPK + head]
                                             : 0xFFFFFFFFFFFFFFFFULL;
        red[t] = c;
        __syncthreads();
        for (int s = 64; s > 0; s >>= 1) {
            if (t < s) {
                unsigned long long o = red[t + s];
                if (o < red[t]) red[t] = o;
            }
            __syncthreads();
        }
        unsigned long long win = red[0];
        if (c == win) head++;                 // indices are unique -> exactly one winner
        if (t == 0) res[r] = (int)(win & 0xFFFFFFFFu);
        __syncthreads();
    }

    // 27 lanes: IoU + center-inside test for each candidate
    if (t < TOPK) {
        int n = res[t];
        float4 a = ((const float4*)anchors)[b * NANCH + n];
        float area_a = (a.z - a.x) * (a.w - a.y);
        float area_g = (gt.z - gt.x) * (gt.w - gt.y);
        float lx = fmaxf(a.x, gt.x), ly = fmaxf(a.y, gt.y);
        float rx = fminf(a.z, gt.z), ry = fminf(a.w, gt.w);
        float w = fmaxf(rx - lx, 0.0f), h = fmaxf(ry - ly, 0.0f);
        float inter = w * h;
        float uni = area_a + area_g - inter;
        siou[t] = __fdiv_rn(inter, uni);

        float acx = (a.x + a.z) * 0.5f, acy = (a.y + a.w) * 0.5f;
        float l  = acx - gt.x;
        float tp = acy - gt.y;
        float rr = gt.z - acx;
        float bb = gt.w - acy;
        float mn = fminf(fminf(l, tp), fminf(rr, bb));
        sing[t] = (mn > 0.01f) ? 1 : 0;
    }
    __syncthreads();

    if (t == 0) {
        double s = 0.0, ss = 0.0;
        for (int k = 0; k < TOPK; k++) {
            double v = (double)siou[k];
            s += v; ss += v * v;
        }
        double mean = s / TOPK;
        double var  = (ss - s * s / TOPK) / (TOPK - 1);   // ddof=1 (unbiased)
        if (var < 0.0) var = 0.0;
        sthr = (float)(mean + sqrt(var));
    }
    __syncthreads();

    if (t < TOPK) {
        int o = bg * TOPK + t;
        g_cand_idx[o] = res[t];
        float iou = siou[t];
        bool pos = (iou >= sthr) && (sing[t] != 0);
        g_cand_iou[o] = pos ? iou : -1.0f;
    }
}

// ---------------- kernel 2: clear match table ----------------
__global__ void init_kernel() {
    int i = blockIdx.x * blockDim.x + threadIdx.x;
    if (i < BATCH * NANCH) g_match[i] = 0ULL;
}

// ---------------- kernel 2b: scatter positives, argmax over gts via atomicMax ----------------
__global__ void scatter_kernel() {
    int i = blockIdx.x * blockDim.x + threadIdx.x;
    if (i >= BATCH * NGT * TOPK) return;
    float iou = g_cand_iou[i];
    if (iou < 0.0f) return;                 // positives always have iou > 0
    int b = i / (NGT * TOPK);
    int g = (i / TOPK) % NGT;
    int n = g_cand_idx[i];
    // bigger iou wins; ties -> smaller g (matches jnp argmax first-occurrence)
    unsigned long long p =
        (((unsigned long long)__float_as_uint(iou)) << 32) | (unsigned)(NGT - 1 - g);
    atomicMax(&g_match[b * NANCH + n], p);
}

// ---------------- kernel 3a: values / indices / matched_gts ----------------
__global__ void scalars_kernel(const float* __restrict__ gts, float* __restrict__ out) {
    int i = blockIdx.x * blockDim.x + threadIdx.x;
    if (i >= BATCH * NANCH) return;
    int b = i / NANCH;
    unsigned long long m = g_match[i];
    float val; int g;
    if (m) {
        g   = NGT - 1 - (int)(m & 0xFFFFFFFFu);
        val = __uint_as_float((unsigned)(m >> 32));
    } else {
        g = 0; val = NEG_INF;               // argmax of all -INF row is 0
    }
    out[i]                 = val;           // anchors_to_gt_values
    out[BATCH * NANCH + i] = (float)g;      // anchors_to_gt_indexs (0 when unmatched)
    float4 gtb = ((const float4*)gts)[b * NGT + g];
    ((float4*)(out + 2 * (size_t)BATCH * NANCH))[i] = gtb;   // matched_gts
}

// ---------------- kernel 3b: token_labels (the 819 MB streaming write) ----------------
__global__ __launch_bounds__(256) void tokens_kernel(const float* __restrict__ tokens,
                                                     float* __restrict__ out) {
    int warp = (blockIdx.x * blockDim.x + threadIdx.x) >> 5;
    int lane = threadIdx.x & 31;
    if (warp >= BATCH * NANCH) return;
    int b = warp / NANCH;
    unsigned long long m = g_match[warp];

    float4* dst = (float4*)(out + (size_t)6 * BATCH * NANCH) + (size_t)warp * (NTOK / 4);
    if (m) {
        int g = NGT - 1 - (int)(m & 0xFFFFFFFFu);
        const float4* src = (const float4*)(tokens + ((size_t)b * NGT + g) * NTOK);
        dst[lane]      = src[lane];
        dst[lane + 32] = src[lane + 32];
    } else {
        float4 z = make_float4(0.f, 0.f, 0.f, 0.f);
        dst[lane] = z;
        float4 z2 = z;
        if (lane == 31) z2.w = 1.0f;        // one-hot at token index 255
        dst[lane + 32] = z2;
    }
}

// ---------------- launch ----------------
extern "C" void kernel_launch(void* const* d_in, const int* in_sizes, int n_in,
                              void* d_out, int out_size) {
    const float* anchors = (const float*)d_in[0];   // [8,100000,4]
    const float* gts     = (const float*)d_in[1];   // [8,64,4]
    const float* tokens  = (const float*)d_in[2];   // [8,64,256]
    float* out = (float*)d_out;

    centers_kernel<<<(BATCH * NANCH + 255) / 256, 256>>>(anchors);
    topk_kernel<<<BATCH * NGT, 128>>>(anchors, gts);
    init_kernel<<<(BATCH * NANCH + 255) / 256, 256>>>();
    scatter_kernel<<<(BATCH * NGT * TOPK + 255) / 256, 256>>>();
    scalars_kernel<<<(BATCH * NANCH + 255) / 256, 256>>>(gts, out);
    tokens_kernel<<<(BATCH * NANCH * 32 + 255) / 256, 256>>>(tokens, out);
}

// round 2
// speedup vs baseline: 1.4309x; 1.4309x over previous
#include <cuda_runtime.h>
#include <stdint.h>
#include <math.h>

#define BATCH 8
#define NANCH 100000
#define NGT   64
#define NTOK  256
#define TOPK  27
#define SPLIT 4
#define SEG   (NANCH / SPLIT)      // 25000 centers per segment
#define SEG4  (SEG / 2)            // 12500 float4 loads (2 centers each)
#define PTHREADS 128
#define MCAND (SPLIT * TOPK)       // 108
#define NEG_INF -100000000.0f

// ---------------- device scratch ----------------
__device__ float2             g_centers[BATCH * NANCH];
__device__ unsigned long long g_part[BATCH * NGT * MCAND];   // per-segment top-27, packed (d2<<32|idx)
__device__ unsigned long long g_match[BATCH * NANCH];        // packed (iou<<32 | 63-g), 0 = unmatched
__device__ int                g_cand_idx[BATCH * NGT * TOPK];
__device__ float              g_cand_iou[BATCH * NGT * TOPK];

// ---------------- kernel 0: centers + clear match table ----------------
__global__ void centers_kernel(const float* __restrict__ anchors) {
    int i = blockIdx.x * blockDim.x + threadIdx.x;
    if (i < BATCH * NANCH) {
        float4 a = ((const float4*)anchors)[i];
        g_centers[i] = make_float2((a.x + a.z) * 0.5f, (a.y + a.w) * 0.5f);
        g_match[i] = 0ULL;
    }
}

// insert p into sorted (ascending) reg array best[0..26]; caller guarantees p < best[26]
#define INSERT27(best, p)                                         \
    {                                                             \
        _Pragma("unroll")                                         \
        for (int k = TOPK - 1; k >= 0; --k) {                     \
            if (k == 0 || (p) >= best[k - 1]) { best[k] = (p); break; } \
            best[k] = best[k - 1];                                \
        }                                                         \
    }

// ---------------- kernel 1: per-(b,g,segment) exact top-27 nearest anchors ----------------
__global__ __launch_bounds__(PTHREADS) void topk_part_kernel(const float* __restrict__ gts) {
    const int blk = blockIdx.x;            // bg * SPLIT + p
    const int p   = blk % SPLIT;
    const int bg  = blk / SPLIT;
    const int b   = bg / NGT;
    const int t   = threadIdx.x;

    const float4 gt = ((const float4*)gts)[bg];
    const float gcx = (gt.x + gt.z) * 0.5f;
    const float gcy = (gt.y + gt.w) * 0.5f;

    const int nbase = p * SEG;
    const float4* __restrict__ cen4 = (const float4*)(g_centers + b * NANCH + nbase);

    unsigned long long best[TOPK];
#pragma unroll
    for (int k = 0; k < TOPK; k++) best[k] = 0xFFFFFFFFFFFFFFFFULL;

    // batched scan: 4 independent float4 loads in flight (MLP=4, 8 centers/batch/thread)
    for (int q0 = t; q0 < SEG4; q0 += PTHREADS * 4) {
        float4 v[4];
        int    qi[4];
#pragma unroll
        for (int j = 0; j < 4; j++) {
            qi[j] = q0 + j * PTHREADS;
            if (qi[j] < SEG4) v[j] = cen4[qi[j]];
        }
#pragma unroll
        for (int j = 0; j < 4; j++) {
            if (qi[j] >= SEG4) continue;
            int n0 = nbase + 2 * qi[j];
            {
                float dx = v[j].x - gcx, dy = v[j].y - gcy;
                float d2 = dx * dx + dy * dy;
                unsigned long long pk =
                    (((unsigned long long)__float_as_uint(d2)) << 32) | (unsigned)n0;
                if (pk < best[TOPK - 1]) INSERT27(best, pk);
            }
            {
                float dx = v[j].z - gcx, dy = v[j].w - gcy;
                float d2 = dx * dx + dy * dy;
                unsigned long long pk =
                    (((unsigned long long)__float_as_uint(d2)) << 32) | (unsigned)(n0 + 1);
                if (pk < best[TOPK - 1]) INSERT27(best, pk);
            }
        }
    }

    // merge 128 sorted lists -> block top-27 (27 rounds of head-min, shuffle reduction)
    __shared__ unsigned long long cand[PTHREADS * TOPK];
    __shared__ unsigned long long warpmin[PTHREADS / 32];
    __shared__ unsigned long long s_win;

#pragma unroll
    for (int k = 0; k < TOPK; k++) cand[t * TOPK + k] = best[k];
    __syncthreads();

    const int lane = t & 31, wid = t >> 5;
    int head = 0;
    for (int r = 0; r < TOPK; r++) {
        unsigned long long c = (head < TOPK) ? cand[t * TOPK + head]
                                             : 0xFFFFFFFFFFFFFFFFULL;
        unsigned long long m = c;
#pragma unroll
        for (int s = 16; s > 0; s >>= 1) {
            unsigned long long o = __shfl_down_sync(0xFFFFFFFFu, m, s);
            if (o < m) m = o;
        }
        if (lane == 0) warpmin[wid] = m;
        __syncthreads();
        if (t == 0) {
            unsigned long long w = warpmin[0];
#pragma unroll
            for (int k = 1; k < PTHREADS / 32; k++)
                if (warpmin[k] < w) w = warpmin[k];
            s_win = w;
        }
        __syncthreads();
        unsigned long long win = s_win;
        if (c == win) head++;              // unique keys -> exactly one owner
        if (t == 0) g_part[bg * MCAND + p * TOPK + r] = win;
        __syncthreads();
    }
}

// ---------------- kernel 2: merge segments, IoU stats, positivity ----------------
__global__ __launch_bounds__(128) void merge_kernel(const float* __restrict__ anchors,
                                                    const float* __restrict__ gts) {
    const int bg = blockIdx.x;
    const int b  = bg / NGT;
    const int t  = threadIdx.x;

    __shared__ unsigned long long sc[MCAND];
    __shared__ int   res[TOPK];
    __shared__ float siou[TOPK];
    __shared__ int   sing[TOPK];
    __shared__ float sthr;

    if (t < MCAND) sc[t] = g_part[bg * MCAND + t];
    __syncthreads();

    if (t < MCAND) {
        unsigned long long mine = sc[t];
        int rank = 0;
        for (int j = 0; j < MCAND; j++) rank += (sc[j] < mine);
        if (rank < TOPK) res[rank] = (int)(mine & 0xFFFFFFFFu);
    }
    __syncthreads();

    const float4 gt = ((const float4*)gts)[bg];
    if (t < TOPK) {
        int n = res[t];
        float4 a = ((const float4*)anchors)[b * NANCH + n];
        float area_a = (a.z - a.x) * (a.w - a.y);
        float area_g = (gt.z - gt.x) * (gt.w - gt.y);
        float lx = fmaxf(a.x, gt.x), ly = fmaxf(a.y, gt.y);
        float rx = fminf(a.z, gt.z), ry = fminf(a.w, gt.w);
        float w = fmaxf(rx - lx, 0.0f), h = fmaxf(ry - ly, 0.0f);
        float inter = w * h;
        float uni = area_a + area_g - inter;
        siou[t] = __fdiv_rn(inter, uni);

        float acx = (a.x + a.z) * 0.5f, acy = (a.y + a.w) * 0.5f;
        float l  = acx - gt.x;
        float tp = acy - gt.y;
        float rr = gt.z - acx;
        float bb = gt.w - acy;
        float mn = fminf(fminf(l, tp), fminf(rr, bb));
        sing[t] = (mn > 0.01f) ? 1 : 0;
    }
    __syncthreads();

    if (t == 0) {
        double s = 0.0, ss = 0.0;
        for (int k = 0; k < TOPK; k++) {
            double v = (double)siou[k];
            s += v; ss += v * v;
        }
        double mean = s / TOPK;
        double var  = (ss - s * s / TOPK) / (TOPK - 1);   // ddof=1
        if (var < 0.0) var = 0.0;
        sthr = (float)(mean + sqrt(var));
    }
    __syncthreads();

    if (t < TOPK) {
        int o = bg * TOPK + t;
        g_cand_idx[o] = res[t];
        float iou = siou[t];
        bool pos = (iou >= sthr) && (sing[t] != 0);
        g_cand_iou[o] = pos ? iou : -1.0f;
    }
}

// ---------------- kernel 3: scatter positives (argmax over gts via atomicMax) ----------------
__global__ void scatter_kernel() {
    int i = blockIdx.x * blockDim.x + threadIdx.x;
    if (i >= BATCH * NGT * TOPK) return;
    float iou = g_cand_iou[i];
    if (iou < 0.0f) return;                // positives always have iou > 0
    int b = i / (NGT * TOPK);
    int g = (i / TOPK) % NGT;
    int n = g_cand_idx[i];
    unsigned long long p =
        (((unsigned long long)__float_as_uint(iou)) << 32) | (unsigned)(NGT - 1 - g);
    atomicMax(&g_match[b * NANCH + n], p);
}

// ---------------- kernel 4: values / indices / matched_gts ----------------
__global__ void scalars_kernel(const float* __restrict__ gts, float* __restrict__ out) {
    int i = blockIdx.x * blockDim.x + threadIdx.x;
    if (i >= BATCH * NANCH) return;
    int b = i / NANCH;
    unsigned long long m = g_match[i];
    float val; int g;
    if (m) {
        g   = NGT - 1 - (int)(m & 0xFFFFFFFFu);
        val = __uint_as_float((unsigned)(m >> 32));
    } else {
        g = 0; val = NEG_INF;
    }
    out[i]                 = val;
    out[BATCH * NANCH + i] = (float)g;
    float4 gtb = ((const float4*)gts)[b * NGT + g];
    ((float4*)(out + 2 * (size_t)BATCH * NANCH))[i] = gtb;
}

// ---------------- kernel 5: token_labels (819 MB streaming write) ----------------
__global__ __launch_bounds__(256) void tokens_kernel(const float* __restrict__ tokens,
                                                     float* __restrict__ out) {
    int warp = (blockIdx.x * blockDim.x + threadIdx.x) >> 5;
    int lane = threadIdx.x & 31;
    if (warp >= BATCH * NANCH) return;
    int b = warp / NANCH;
    unsigned long long m = g_match[warp];

    float4* dst = (float4*)(out + (size_t)6 * BATCH * NANCH) + (size_t)warp * (NTOK / 4);
    if (m) {
        int g = NGT - 1 - (int)(m & 0xFFFFFFFFu);
        const float4* src = (const float4*)(tokens + ((size_t)b * NGT + g) * NTOK);
        dst[lane]      = src[lane];
        dst[lane + 32] = src[lane + 32];
    } else {
        float4 z = make_float4(0.f, 0.f, 0.f, 0.f);
        dst[lane] = z;
        float4 z2 = z;
        if (lane == 31) z2.w = 1.0f;       // one-hot at token index 255
        dst[lane + 32] = z2;
    }
}

// ---------------- launch ----------------
extern "C" void kernel_launch(void* const* d_in, const int* in_sizes, int n_in,
                              void* d_out, int out_size) {
    const float* anchors = (const float*)d_in[0];   // [8,100000,4]
    const float* gts     = (const float*)d_in[1];   // [8,64,4]
    const float* tokens  = (const float*)d_in[2];   // [8,64,256]
    float* out = (float*)d_out;

    centers_kernel<<<(BATCH * NANCH + 255) / 256, 256>>>(anchors);
    topk_part_kernel<<<BATCH * NGT * SPLIT, PTHREADS>>>(gts);
    merge_kernel<<<BATCH * NGT, 128>>>(anchors, gts);
    scatter_kernel<<<(BATCH * NGT * TOPK + 255) / 256, 256>>>();
    scalars_kernel<<<(BATCH * NANCH + 255) / 256, 256>>>(gts, out);
    tokens_kernel<<<(BATCH * NANCH * 32 + 255) / 256, 256>>>(tokens, out);
}

// round 4
// speedup vs baseline: 25.5794x; 17.8767x over previous
#include <cuda_runtime.h>
#include <stdint.h>
#include <math.h>

#define BATCH 8
#define NANCH 100000
#define NGT   64
#define NTOK  256
#define TOPK  27
#define NEG_INF -100000000.0f

#define BINS   64
#define NBIN   (BINS * BINS)        // 4096 bins per batch
#define INVBIN 0.0625f              // 1/16 px
#define U64MAX 0xFFFFFFFFFFFFFFFFULL

// ---------------- device scratch ----------------
__device__ float2             g_centers [BATCH * NANCH];
__device__ int                g_hist    [BATCH * NBIN];
__device__ int                g_fill    [BATCH * NBIN];
__device__ int                g_binstart[BATCH * (NBIN + 1)];
__device__ float4             g_sorted  [BATCH * NANCH];   // {cx, cy, idx_bits, 0}
__device__ unsigned long long g_match   [BATCH * NANCH];   // packed (iou<<32 | 63-g), 0 = unmatched

// ---------------- kernel 0: zero hist/fill ----------------
__global__ void zero_kernel() {
    int i = blockIdx.x * blockDim.x + threadIdx.x;
    if (i < BATCH * NBIN) { g_hist[i] = 0; g_fill[i] = 0; }
}

// ---------------- kernel 1: centers + histogram + clear match ----------------
__global__ void prep_kernel(const float* __restrict__ anchors) {
    int i = blockIdx.x * blockDim.x + threadIdx.x;
    if (i >= BATCH * NANCH) return;
    float4 a = ((const float4*)anchors)[i];
    float cx = (a.x + a.z) * 0.5f;
    float cy = (a.y + a.w) * 0.5f;
    g_centers[i] = make_float2(cx, cy);
    g_match[i] = 0ULL;
    int b  = i / NANCH;
    int bx = min(BINS - 1, max(0, (int)(cx * INVBIN)));
    int by = min(BINS - 1, max(0, (int)(cy * INVBIN)));
    atomicAdd(&g_hist[b * NBIN + by * BINS + bx], 1);
}

// ---------------- kernel 2: per-batch exclusive prefix over 4096 bins ----------------
__global__ __launch_bounds__(1024) void prefix_kernel() {
    const int b = blockIdx.x, t = threadIdx.x;
    int c[4];
    int base = b * NBIN + t * 4;
#pragma unroll
    for (int j = 0; j < 4; j++) c[j] = g_hist[base + j];
    int sum = c[0] + c[1] + c[2] + c[3];

    __shared__ int sc[1024];
    sc[t] = sum;
    __syncthreads();
    for (int off = 1; off < 1024; off <<= 1) {
        int v = (t >= off) ? sc[t - off] : 0;
        __syncthreads();
        sc[t] += v;
        __syncthreads();
    }
    int run = sc[t] - sum;                      // exclusive prefix
    int ob = b * (NBIN + 1) + t * 4;
#pragma unroll
    for (int j = 0; j < 4; j++) { g_binstart[ob + j] = run; run += c[j]; }
    if (t == 1023) g_binstart[b * (NBIN + 1) + NBIN] = run;
}

// ---------------- kernel 3: counting-sort scatter ----------------
__global__ void binscatter_kernel() {
    int i = blockIdx.x * blockDim.x + threadIdx.x;
    if (i >= BATCH * NANCH) return;
    float2 c = g_centers[i];
    int b = i / NANCH, n = i % NANCH;
    int bx = min(BINS - 1, max(0, (int)(c.x * INVBIN)));
    int by = min(BINS - 1, max(0, (int)(c.y * INVBIN)));
    int bin = by * BINS + bx;
    int ofs = atomicAdd(&g_fill[b * NBIN + bin], 1);
    int dst = g_binstart[b * (NBIN + 1) + bin] + ofs;
    g_sorted[b * NANCH + dst] =
        make_float4(c.x, c.y, __uint_as_float((unsigned)n), 0.0f);
}

// insert p into sorted (ascending) reg array best[0..26]; caller guarantees p < best[26]
#define INSERT27(best, p)                                               \
    {                                                                   \
        _Pragma("unroll")                                               \
        for (int k = TOPK - 1; k >= 0; --k) {                           \
            if (k == 0 || (p) >= best[k - 1]) { best[k] = (p); break; } \
            best[k] = best[k - 1];                                      \
        }                                                               \
    }

// ---------------- kernel 4: per-gt windowed exact top-27 + IoU + scatter ----------------
__global__ __launch_bounds__(32) void gt_kernel(const float* __restrict__ anchors,
                                                const float* __restrict__ gts) {
    const int bg   = blockIdx.x;
    const int b    = bg / NGT;
    const int lane = threadIdx.x;

    const float4 gt = ((const float4*)gts)[bg];
    const float gcx = (gt.x + gt.z) * 0.5f;
    const float gcy = (gt.y + gt.w) * 0.5f;

    const float4* __restrict__ sc = g_sorted + b * NANCH;
    const int*    __restrict__ bs = g_binstart + b * (NBIN + 1);

    __shared__ unsigned long long skey[TOPK];
    __shared__ float siou[TOPK];
    __shared__ int   sing[TOPK];
    __shared__ float sthr;

    float W = 16.0f;
    for (;;) {
        int bx0 = max(0, (int)((gcx - W) * INVBIN));
        int bx1 = min(BINS - 1, (int)((gcx + W) * INVBIN));
        int by0 = max(0, (int)((gcy - W) * INVBIN));
        int by1 = min(BINS - 1, (int)((gcy + W) * INVBIN));

        int total = 0;
        for (int by = by0; by <= by1; by++)
            total += bs[by * BINS + bx1 + 1] - bs[by * BINS + bx0];

        // per-lane sorted top-27 over window row segments
        unsigned long long best[TOPK];
#pragma unroll
        for (int k = 0; k < TOPK; k++) best[k] = U64MAX;

        for (int by = by0; by <= by1; by++) {
            int s = bs[by * BINS + bx0];
            int e = bs[by * BINS + bx1 + 1];
            for (int i = s + lane; i < e; i += 32) {
                float4 v = sc[i];
                float dx = v.x - gcx, dy = v.y - gcy;
                float d2 = dx * dx + dy * dy;
                // integer-domain filter: positive-float bits are order-isomorphic,
                // and the 0xFFFFFFFF sentinel (NaN as float!) compares correctly here
                if (__float_as_uint(d2) <= (unsigned)(best[TOPK - 1] >> 32)) {
                    unsigned long long pk =
                        (((unsigned long long)__float_as_uint(d2)) << 32) |
                        __float_as_uint(v.z);
                    if (pk < best[TOPK - 1]) INSERT27(best, pk);
                }
            }
        }

        // warp merge: 27 rounds of head-min
        int head = 0;
        for (int r = 0; r < TOPK; r++) {
            unsigned long long c = (head < TOPK) ? best[head] : U64MAX;
            unsigned long long m = c;
#pragma unroll
            for (int s = 16; s > 0; s >>= 1) {
                unsigned long long o = __shfl_xor_sync(0xFFFFFFFFu, m, s);
                if (o < m) m = o;
            }
            if (lane == 0) skey[r] = m;
            if (c == m) head++;
        }
        __syncwarp();

        bool full_canvas = (bx0 == 0 && bx1 == BINS - 1 && by0 == 0 && by1 == BINS - 1);
        float d27sq = __uint_as_float((unsigned)(skey[TOPK - 1] >> 32));
        if ((total >= TOPK && d27sq < W * W * 0.999f) || full_canvas) break;
        W *= 2.0f;
    }

    // IoU + center-inside for the 27 winners
    if (lane < TOPK) {
        int n = (int)(skey[lane] & 0xFFFFFFFFu);
        float4 a = ((const float4*)anchors)[b * NANCH + n];
        float area_a = (a.z - a.x) * (a.w - a.y);
        float area_g = (gt.z - gt.x) * (gt.w - gt.y);
        float lx = fmaxf(a.x, gt.x), ly = fmaxf(a.y, gt.y);
        float rx = fminf(a.z, gt.z), ry = fminf(a.w, gt.w);
        float w = fmaxf(rx - lx, 0.0f), h = fmaxf(ry - ly, 0.0f);
        float inter = w * h;
        float uni = area_a + area_g - inter;
        siou[lane] = __fdiv_rn(inter, uni);

        float acx = (a.x + a.z) * 0.5f, acy = (a.y + a.w) * 0.5f;
        float l  = acx - gt.x;
        float tp = acy - gt.y;
        float rr = gt.z - acx;
        float bb = gt.w - acy;
        float mn = fminf(fminf(l, tp), fminf(rr, bb));
        sing[lane] = (mn > 0.01f) ? 1 : 0;
    }
    __syncwarp();

    if (lane == 0) {
        double s = 0.0, ss = 0.0;
        for (int k = 0; k < TOPK; k++) {
            double v = (double)siou[k];
            s += v; ss += v * v;
        }
        double mean = s / TOPK;
        double var  = (ss - s * s / TOPK) / (TOPK - 1);   // ddof=1 (unbiased)
        if (var < 0.0) var = 0.0;
        sthr = (float)(mean + sqrt(var));
    }
    __syncwarp();

    // fused scatter: argmax over gts via packed atomicMax (positives have iou > 0)
    if (lane < TOPK) {
        float iou = siou[lane];
        if (iou >= sthr && sing[lane]) {
            int n = (int)(skey[lane] & 0xFFFFFFFFu);
            int g = bg % NGT;
            unsigned long long p =
                (((unsigned long long)__float_as_uint(iou)) << 32) |
                (unsigned)(NGT - 1 - g);
            atomicMax(&g_match[b * NANCH + n], p);
        }
    }
}

// ---------------- kernel 5: values / indices / matched_gts ----------------
__global__ void scalars_kernel(const float* __restrict__ gts, float* __restrict__ out) {
    int i = blockIdx.x * blockDim.x + threadIdx.x;
    if (i >= BATCH * NANCH) return;
    int b = i / NANCH;
    unsigned long long m = g_match[i];
    float val; int g;
    if (m) {
        g   = NGT - 1 - (int)(m & 0xFFFFFFFFu);
        val = __uint_as_float((unsigned)(m >> 32));
    } else {
        g = 0; val = NEG_INF;
    }
    out[i]                 = val;
    out[BATCH * NANCH + i] = (float)g;
    float4 gtb = ((const float4*)gts)[b * NGT + g];
    ((float4*)(out + 2 * (size_t)BATCH * NANCH))[i] = gtb;
}

// ---------------- kernel 6: token_labels (819 MB streaming write) ----------------
__global__ __launch_bounds__(256) void tokens_kernel(const float* __restrict__ tokens,
                                                     float* __restrict__ out) {
    int warp = (blockIdx.x * blockDim.x + threadIdx.x) >> 5;
    int lane = threadIdx.x & 31;
    if (warp >= BATCH * NANCH) return;
    int b = warp / NANCH;
    unsigned long long m = g_match[warp];

    float4* dst = (float4*)(out + (size_t)6 * BATCH * NANCH) + (size_t)warp * (NTOK / 4);
    if (m) {
        int g = NGT - 1 - (int)(m & 0xFFFFFFFFu);
        const float4* src = (const float4*)(tokens + ((size_t)b * NGT + g) * NTOK);
        dst[lane]      = src[lane];
        dst[lane + 32] = src[lane + 32];
    } else {
        float4 z = make_float4(0.f, 0.f, 0.f, 0.f);
        dst[lane] = z;
        float4 z2 = z;
        if (lane == 31) z2.w = 1.0f;       // one-hot at token index 255
        dst[lane + 32] = z2;
    }
}

// ---------------- launch ----------------
extern "C" void kernel_launch(void* const* d_in, const int* in_sizes, int n_in,
                              void* d_out, int out_size) {
    const float* anchors = (const float*)d_in[0];   // [8,100000,4]
    const float* gts     = (const float*)d_in[1];   // [8,64,4]
    const float* tokens  = (const float*)d_in[2];   // [8,64,256]
    float* out = (float*)d_out;

    zero_kernel<<<(BATCH * NBIN + 255) / 256, 256>>>();
    prep_kernel<<<(BATCH * NANCH + 255) / 256, 256>>>(anchors);
    prefix_kernel<<<BATCH, 1024>>>();
    binscatter_kernel<<<(BATCH * NANCH + 255) / 256, 256>>>();
    gt_kernel<<<BATCH * NGT, 32>>>(anchors, gts);
    scalars_kernel<<<(BATCH * NANCH + 255) / 256, 256>>>(gts, out);
    tokens_kernel<<<(BATCH * NANCH * 32 + 255) / 256, 256>>>(tokens, out);
}

// round 5
// speedup vs baseline: 28.9825x; 1.1330x over previous
#include <cuda_runtime.h>
#include <stdint.h>
#include <math.h>

#define BATCH 8
#define NANCH 100000
#define NGT   64
#define NTOK  256
#define TOPK  27
#define NEG_INF -100000000.0f

#define BINS   64
#define NBIN   (BINS * BINS)        // 4096 bins per batch
#define INVBIN 0.0625f              // 1/16 px
#define U64MAX 0xFFFFFFFFFFFFFFFFULL

// ---------------- device scratch ----------------
__device__ float2             g_centers [BATCH * NANCH];
__device__ int                g_hist    [BATCH * NBIN];
__device__ int                g_fill    [BATCH * NBIN];
__device__ int                g_binstart[BATCH * (NBIN + 1)];
__device__ int                g_order   [BATCH * NANCH];    // counting-sorted anchor indices
__device__ unsigned long long g_match   [BATCH * NANCH];    // packed (iou<<32 | 63-g), 0 = unmatched

// ---------------- kernel 0: zero hist/fill ----------------
__global__ void zero_kernel() {
    int i = blockIdx.x * blockDim.x + threadIdx.x;
    if (i < BATCH * NBIN) { g_hist[i] = 0; g_fill[i] = 0; }
}

// ---------------- kernel 1: centers + histogram + clear match ----------------
__global__ void prep_kernel(const float* __restrict__ anchors) {
    int i = blockIdx.x * blockDim.x + threadIdx.x;
    if (i >= BATCH * NANCH) return;
    float4 a = ((const float4*)anchors)[i];
    float cx = (a.x + a.z) * 0.5f;
    float cy = (a.y + a.w) * 0.5f;
    g_centers[i] = make_float2(cx, cy);
    g_match[i] = 0ULL;
    int b  = i / NANCH;
    int bx = min(BINS - 1, max(0, (int)(cx * INVBIN)));
    int by = min(BINS - 1, max(0, (int)(cy * INVBIN)));
    atomicAdd(&g_hist[b * NBIN + by * BINS + bx], 1);
}

// ---------------- kernel 2: per-batch exclusive prefix over 4096 bins ----------------
__global__ __launch_bounds__(1024) void prefix_kernel() {
    const int b = blockIdx.x, t = threadIdx.x;
    int c[4];
    int base = b * NBIN + t * 4;
#pragma unroll
    for (int j = 0; j < 4; j++) c[j] = g_hist[base + j];
    int sum = c[0] + c[1] + c[2] + c[3];

    __shared__ int sc[1024];
    sc[t] = sum;
    __syncthreads();
    for (int off = 1; off < 1024; off <<= 1) {
        int v = (t >= off) ? sc[t - off] : 0;
        __syncthreads();
        sc[t] += v;
        __syncthreads();
    }
    int run = sc[t] - sum;                      // exclusive prefix
    int ob = b * (NBIN + 1) + t * 4;
#pragma unroll
    for (int j = 0; j < 4; j++) { g_binstart[ob + j] = run; run += c[j]; }
    if (t == 1023) g_binstart[b * (NBIN + 1) + NBIN] = run;
}

// ---------------- kernel 3: counting-sort scatter (4B payload: index only) ----------------
__global__ void binscatter_kernel() {
    int i = blockIdx.x * blockDim.x + threadIdx.x;
    if (i >= BATCH * NANCH) return;
    float2 c = g_centers[i];
    int b = i / NANCH, n = i % NANCH;
    int bx = min(BINS - 1, max(0, (int)(c.x * INVBIN)));
    int by = min(BINS - 1, max(0, (int)(c.y * INVBIN)));
    int bin = by * BINS + bx;
    int ofs = atomicAdd(&g_fill[b * NBIN + bin], 1);
    int dst = g_binstart[b * (NBIN + 1) + bin] + ofs;
    g_order[b * NANCH + dst] = n;
}

// insert p into sorted (ascending) reg array best[0..26]; caller guarantees p < best[26]
#define INSERT27(best, p)                                               \
    {                                                                   \
        _Pragma("unroll")                                               \
        for (int k = TOPK - 1; k >= 0; --k) {                           \
            if (k == 0 || (p) >= best[k - 1]) { best[k] = (p); break; } \
            best[k] = best[k - 1];                                      \
        }                                                               \
    }

// ---------------- kernel 4: per-gt windowed exact top-27 + IoU + scatter ----------------
__global__ __launch_bounds__(32) void gt_kernel(const float* __restrict__ anchors,
                                                const float* __restrict__ gts) {
    const int bg   = blockIdx.x;
    const int b    = bg / NGT;
    const int lane = threadIdx.x;

    const float4 gt = ((const float4*)gts)[bg];
    const float gcx = (gt.x + gt.z) * 0.5f;
    const float gcy = (gt.y + gt.w) * 0.5f;

    const int*    __restrict__ ord = g_order   + b * NANCH;
    const float2* __restrict__ cen = g_centers + b * NANCH;
    const int*    __restrict__ bs  = g_binstart + b * (NBIN + 1);

    __shared__ unsigned long long skey[TOPK];
    __shared__ float siou[TOPK];
    __shared__ int   sing[TOPK];
    __shared__ float sthr;

    float W = 16.0f;
    for (;;) {
        int bx0 = max(0, (int)((gcx - W) * INVBIN));
        int bx1 = min(BINS - 1, (int)((gcx + W) * INVBIN));
        int by0 = max(0, (int)((gcy - W) * INVBIN));
        int by1 = min(BINS - 1, (int)((gcy + W) * INVBIN));

        int total = 0;
        for (int by = by0; by <= by1; by++)
            total += bs[by * BINS + bx1 + 1] - bs[by * BINS + bx0];

        // per-lane sorted top-27 over window row segments
        unsigned long long best[TOPK];
#pragma unroll
        for (int k = 0; k < TOPK; k++) best[k] = U64MAX;

        for (int by = by0; by <= by1; by++) {
            int s = bs[by * BINS + bx0];
            int e = bs[by * BINS + bx1 + 1];
            for (int i = s + lane; i < e; i += 32) {
                int n = ord[i];
                float2 c = cen[n];
                float dx = c.x - gcx, dy = c.y - gcy;
                float d2 = dx * dx + dy * dy;
                // integer-domain filter: positive-float bits are order-isomorphic,
                // and the 0xFFFFFFFF sentinel (NaN as float!) compares correctly here
                if (__float_as_uint(d2) <= (unsigned)(best[TOPK - 1] >> 32)) {
                    unsigned long long pk =
                        (((unsigned long long)__float_as_uint(d2)) << 32) |
                        (unsigned)n;
                    if (pk < best[TOPK - 1]) INSERT27(best, pk);
                }
            }
        }

        // warp merge: 27 rounds of head-min
        int head = 0;
        for (int r = 0; r < TOPK; r++) {
            unsigned long long c = (head < TOPK) ? best[head] : U64MAX;
            unsigned long long m = c;
#pragma unroll
            for (int s = 16; s > 0; s >>= 1) {
                unsigned long long o = __shfl_xor_sync(0xFFFFFFFFu, m, s);
                if (o < m) m = o;
            }
            if (lane == 0) skey[r] = m;
            if (c == m) head++;
        }
        __syncwarp();

        bool full_canvas = (bx0 == 0 && bx1 == BINS - 1 && by0 == 0 && by1 == BINS - 1);
        float d27sq = __uint_as_float((unsigned)(skey[TOPK - 1] >> 32));
        if ((total >= TOPK && d27sq < W * W * 0.999f) || full_canvas) break;
        W *= 2.0f;
    }

    // IoU + center-inside for the 27 winners
    if (lane < TOPK) {
        int n = (int)(skey[lane] & 0xFFFFFFFFu);
        float4 a = ((const float4*)anchors)[b * NANCH + n];
        float area_a = (a.z - a.x) * (a.w - a.y);
        float area_g = (gt.z - gt.x) * (gt.w - gt.y);
        float lx = fmaxf(a.x, gt.x), ly = fmaxf(a.y, gt.y);
        float rx = fminf(a.z, gt.z), ry = fminf(a.w, gt.w);
        float w = fmaxf(rx - lx, 0.0f), h = fmaxf(ry - ly, 0.0f);
        float inter = w * h;
        float uni = area_a + area_g - inter;
        siou[lane] = __fdiv_rn(inter, uni);

        float acx = (a.x + a.z) * 0.5f, acy = (a.y + a.w) * 0.5f;
        float l  = acx - gt.x;
        float tp = acy - gt.y;
        float rr = gt.z - acx;
        float bb = gt.w - acy;
        float mn = fminf(fminf(l, tp), fminf(rr, bb));
        sing[lane] = (mn > 0.01f) ? 1 : 0;
    }
    __syncwarp();

    if (lane == 0) {
        double s = 0.0, ss = 0.0;
        for (int k = 0; k < TOPK; k++) {
            double v = (double)siou[k];
            s += v; ss += v * v;
        }
        double mean = s / TOPK;
        double var  = (ss - s * s / TOPK) / (TOPK - 1);   // ddof=1 (unbiased)
        if (var < 0.0) var = 0.0;
        sthr = (float)(mean + sqrt(var));
    }
    __syncwarp();

    // fused scatter: argmax over gts via packed atomicMax (positives have iou > 0)
    if (lane < TOPK) {
        float iou = siou[lane];
        if (iou >= sthr && sing[lane]) {
            int n = (int)(skey[lane] & 0xFFFFFFFFu);
            int g = bg % NGT;
            unsigned long long p =
                (((unsigned long long)__float_as_uint(iou)) << 32) |
                (unsigned)(NGT - 1 - g);
            atomicMax(&g_match[b * NANCH + n], p);
        }
    }
}

// ---------------- kernel 5: fused outputs — scalars + matched_gts + token_labels ----------------
__global__ __launch_bounds__(256) void output_kernel(const float* __restrict__ gts,
                                                     const float* __restrict__ tokens,
                                                     float* __restrict__ out) {
    int warp = (blockIdx.x * blockDim.x + threadIdx.x) >> 5;
    int lane = threadIdx.x & 31;
    if (warp >= BATCH * NANCH) return;
    int b = warp / NANCH;
    unsigned long long m = g_match[warp];   // same address across warp -> broadcast

    int g; float val;
    if (m) {
        g   = NGT - 1 - (int)(m & 0xFFFFFFFFu);
        val = __uint_as_float((unsigned)(m >> 32));
    } else {
        g = 0; val = NEG_INF;               // argmax of all -INF row is 0
    }

    if (lane == 0) {
        out[warp]                 = val;                       // values
        out[BATCH * NANCH + warp] = (float)g;                  // indices
        float4 gtb = ((const float4*)gts)[b * NGT + g];
        ((float4*)(out + 2 * (size_t)BATCH * NANCH))[warp] = gtb;  // matched_gts
    }

    float4* dst = (float4*)(out + (size_t)6 * BATCH * NANCH) + (size_t)warp * (NTOK / 4);
    if (m) {
        const float4* src = (const float4*)(tokens + ((size_t)b * NGT + g) * NTOK);
        __stcs(dst + lane,      __ldg(src + lane));
        __stcs(dst + lane + 32, __ldg(src + lane + 32));
    } else {
        float4 z = make_float4(0.f, 0.f, 0.f, 0.f);
        __stcs(dst + lane, z);
        float4 z2 = z;
        if (lane == 31) z2.w = 1.0f;        // one-hot at token index 255
        __stcs(dst + lane + 32, z2);
    }
}

// ---------------- launch ----------------
extern "C" void kernel_launch(void* const* d_in, const int* in_sizes, int n_in,
                              void* d_out, int out_size) {
    const float* anchors = (const float*)d_in[0];   // [8,100000,4]
    const float* gts     = (const float*)d_in[1];   // [8,64,4]
    const float* tokens  = (const float*)d_in[2];   // [8,64,256]
    float* out = (float*)d_out;

    zero_kernel<<<(BATCH * NBIN + 255) / 256, 256>>>();
    prep_kernel<<<(BATCH * NANCH + 255) / 256, 256>>>(anchors);
    prefix_kernel<<<BATCH, 1024>>>();
    binscatter_kernel<<<(BATCH * NANCH + 255) / 256, 256>>>();
    gt_kernel<<<BATCH * NGT, 32>>>(anchors, gts);
    output_kernel<<<(BATCH * NANCH * 32 + 255) / 256, 256>>>(gts, tokens, out);
}